// round 12
// baseline (speedup 1.0000x reference)
#include <cuda_runtime.h>
#include <cuda_bf16.h>

// C[i, j] = A[i, i] * B[i, j]   with N = M = 8192, fp32.
// R11 (ILP=8, one row/block): kernel 74.5us @ 81.7% DRAM / 6470 GB/s —
// at the effective HBM ceiling. Final probe: persistent grid-stride form.
// Grid = 2368 blocks (16 per SM-equivalent), each block strides over
// half-row chunks (1024 float4 = 256 thr x ILP 4). Same memory pattern,
// no 55-wave launch tail, high occupancy (ILP=4 reg class).

static constexpr int N = 8192;
static constexpr int VEC_PER_ROW = N / 4;              // 2048
static constexpr int ILP = 4;
static constexpr int THREADS = 256;
static constexpr int VEC_PER_CHUNK = THREADS * ILP;    // 1024 = half row
static constexpr int NUM_CHUNKS = (N * VEC_PER_ROW) / VEC_PER_CHUNK;  // 16384
static constexpr int GRID = 2368;                      // 148 SMs * 16

__global__ __launch_bounds__(THREADS)
void diag_scale_kernel(const float* __restrict__ A,
                       const float4* __restrict__ B,
                       float4* __restrict__ C) {
    for (int chunk = blockIdx.x; chunk < NUM_CHUNKS; chunk += GRID) {
        int row = chunk >> 1;  // chunk = half row; diag uniform per chunk
        float d = __ldg(&A[(long long)row * (N + 1)]);

        long long base = (long long)chunk * VEC_PER_CHUNK + threadIdx.x;

        float4 b0 = __ldcs(&B[base + 0 * THREADS]);
        float4 b1 = __ldcs(&B[base + 1 * THREADS]);
        float4 b2 = __ldcs(&B[base + 2 * THREADS]);
        float4 b3 = __ldcs(&B[base + 3 * THREADS]);

        float4 c0, c1, c2, c3;
        c0.x = d * b0.x; c0.y = d * b0.y; c0.z = d * b0.z; c0.w = d * b0.w;
        c1.x = d * b1.x; c1.y = d * b1.y; c1.z = d * b1.z; c1.w = d * b1.w;
        c2.x = d * b2.x; c2.y = d * b2.y; c2.z = d * b2.z; c2.w = d * b2.w;
        c3.x = d * b3.x; c3.y = d * b3.y; c3.z = d * b3.z; c3.w = d * b3.w;

        __stcs(&C[base + 0 * THREADS], c0);
        __stcs(&C[base + 1 * THREADS], c1);
        __stcs(&C[base + 2 * THREADS], c2);
        __stcs(&C[base + 3 * THREADS], c3);
    }
}

extern "C" void kernel_launch(void* const* d_in, const int* in_sizes, int n_in,
                              void* d_out, int out_size) {
    const float*  A = (const float*)d_in[0];
    const float4* B = (const float4*)d_in[1];
    float4*       C = (float4*)d_out;

    diag_scale_kernel<<<GRID, THREADS>>>(A, B, C);
}